// round 10
// baseline (speedup 1.0000x reference)
#include <cuda_runtime.h>
#include <cuda_fp16.h>
#include <cstdint>

// ---------------------------------------------------------------------------
// LSTM cell, fp16 mma.sync (m16n8k16) GEMM + fused epilogue.
//  Pre-pass 1: WT[gate*2048+n][k] = half(W[k][n]),  k = [x-phase | h-phase]
//  Pre-pass 2: XH[b][k] = half([x|h][b][k])
//  Main: CTA = 128 rows x (4 gates x 32 cols), fp32 acc in regs, BK=64,
//        NBUF=3, 2 CTAs/SM; k32-packed B ldsm4 + pipelined A fragments.
//  Out: [h_t ; c_t], fp32.
// ---------------------------------------------------------------------------

#define HD    2048
#define BB    4096
#define KTOT  4096
#define BM    128
#define BN    32            // cols per gate per CTA
#define BK    64            // halves per stage
#define NSTG  (KTOT/BK)     // 64
#define NBUF  3
#define AST   72            // smem stride in halves (padded, conflict-free)
#define BST   72
#define A_HALVES (BM*AST)                 // 9216
#define B_HALVES (128*BST)                // 9216  (4 gates x 32 cols)
#define STG_HALVES (A_HALVES + B_HALVES)  // 18432 (36864 B)
#define SMEM_BYTES (NBUF*STG_HALVES*2)    // 110592

__device__ __half d_WT[(size_t)4*2048*4096];   // 64 MB
__device__ __half d_XH[(size_t)4096*4096];     // 32 MB

__device__ __forceinline__ uint32_t su32(const void* p) {
    return (uint32_t)__cvta_generic_to_shared(p);
}
__device__ __forceinline__ void cp16(uint32_t d, const void* s) {
    asm volatile("cp.async.cg.shared.global [%0], [%1], 16;" :: "r"(d), "l"(s));
}
__device__ __forceinline__ void ldsm4(uint32_t* r, uint32_t a) {
    asm volatile("ldmatrix.sync.aligned.m8n8.x4.shared.b16 {%0,%1,%2,%3}, [%4];"
                 : "=r"(r[0]), "=r"(r[1]), "=r"(r[2]), "=r"(r[3]) : "r"(a));
}
__device__ __forceinline__ void mma16816(float* c, const uint32_t* a, const uint32_t* b) {
    asm volatile("mma.sync.aligned.m16n8k16.row.col.f32.f16.f16.f32 "
                 "{%0,%1,%2,%3}, {%4,%5,%6,%7}, {%8,%9}, {%0,%1,%2,%3};"
                 : "+f"(c[0]), "+f"(c[1]), "+f"(c[2]), "+f"(c[3])
                 : "r"(a[0]), "r"(a[1]), "r"(a[2]), "r"(a[3]), "r"(b[0]), "r"(b[1]));
}

// ---- pre-pass: transpose + convert weights: WT[g*2048+n][ph*2048+k] ----
__global__ void prep_w(const float* __restrict__ w0, const float* __restrict__ w1,
                       const float* __restrict__ w2, const float* __restrict__ w3,
                       const float* __restrict__ w4, const float* __restrict__ w5,
                       const float* __restrict__ w6, const float* __restrict__ w7) {
    __shared__ float t[32][33];
    const int z = blockIdx.z;                 // phase = z>>2, gate = z&3
    const float* W;
    switch (z) {
        case 0: W = w0; break; case 1: W = w1; break;
        case 2: W = w2; break; case 3: W = w3; break;
        case 4: W = w4; break; case 5: W = w5; break;
        case 6: W = w6; break; default: W = w7; break;
    }
    const int k0 = blockIdx.x * 32, n0 = blockIdx.y * 32;
    const int tx = threadIdx.x, ty = threadIdx.y;
    #pragma unroll
    for (int j = 0; j < 4; j++)
        t[ty + j * 8][tx] = W[(size_t)(k0 + ty + j * 8) * HD + n0 + tx];
    __syncthreads();
    const int gate = z & 3, phase = z >> 2;
    #pragma unroll
    for (int j = 0; j < 4; j++)
        d_WT[(size_t)(gate * 2048 + n0 + ty + j * 8) * KTOT + phase * 2048 + k0 + tx] =
            __float2half_rn(t[tx][ty + j * 8]);
}

// ---- pre-pass: pack + convert activations: XH[b] = [x | h] ----
__global__ void prep_a(const float* __restrict__ x, const float* __restrict__ h) {
    const int idx = blockIdx.x * 256 + threadIdx.x;    // one float4 -> 4 halves
    const int b = idx >> 10;
    const int k = (idx & 1023) * 4;
    const float* s = (k < HD) ? (x + (size_t)b * HD + k)
                              : (h + (size_t)b * HD + (k - HD));
    float4 v = *(const float4*)s;
    __half2 lo = __floats2half2_rn(v.x, v.y);
    __half2 hi = __floats2half2_rn(v.z, v.w);
    *(uint2*)(d_XH + (size_t)b * KTOT + k) =
        make_uint2(*(uint32_t*)&lo, *(uint32_t*)&hi);
}

// ---- main fused GEMM + LSTM epilogue ----
__global__ void __launch_bounds__(256, 2)
lstm_hmma(const float* __restrict__ cin,
          const float* __restrict__ bi, const float* __restrict__ bf,
          const float* __restrict__ bo, const float* __restrict__ bc,
          float* __restrict__ out) {
    extern __shared__ __half smem[];
    const int tid = threadIdx.x, lane = tid & 31, warp = tid >> 5;
    const int warpM = warp & 1;        // 2 warps along M (64 rows each)
    const int warpN = warp >> 1;       // 4 warps along N (8 cols/gate each)
    const int rowBase = blockIdx.x * BM;
    const int colBase = blockIdx.y * BN;

    float acc[4][4][4];                // [gate][mtile][frag]
    #pragma unroll
    for (int g = 0; g < 4; g++)
        #pragma unroll
        for (int m = 0; m < 4; m++)
            #pragma unroll
            for (int r = 0; r < 4; r++) acc[g][m][r] = 0.0f;

    // A ldsm4 per-lane offsets: matrices (m0-7,k0-7),(m8-15,k0-7),(m0-7,k8-15),(m8-15,k8-15)
    const int mi = lane >> 3;
    const int aRow = warpM * 64 + (lane & 7) + (mi & 1) * 8;     // + mtile*16
    const int aKoff = (mi >> 1) * 8;                             // + k16*16
    // B k32-packed ldsm4: matrices (n8,k0-7),(n8,k8-15),(n8,k16-23),(n8,k24-31)
    const int bRow = warpN * 8 + (lane & 7);                     // + g*32
    const int bKoff = mi * 8;                                    // + j*32

    auto load_stage = [&](int s, int buf) {
        __half* st = smem + buf * STG_HALVES;
        const int kb = s * BK;
        #pragma unroll
        for (int i = 0; i < 4; i++) {                 // A: 1024 x 16B
            const int ci = i * 256 + tid;
            const int r = ci >> 3, kc = ci & 7;
            cp16(su32(st + r * AST + kc * 8),
                 d_XH + (size_t)(rowBase + r) * KTOT + kb + kc * 8);
        }
        __half* sb = st + A_HALVES;
        #pragma unroll
        for (int i = 0; i < 4; i++) {                 // B: 1024 x 16B
            const int ci = i * 256 + tid;
            const int n = ci >> 3, kc = ci & 7;
            const int g = n >> 5, nc = colBase + (n & 31);
            cp16(su32(sb + n * BST + kc * 8),
                 d_WT + (size_t)(g * 2048 + nc) * KTOT + kb + kc * 8);
        }
        asm volatile("cp.async.commit_group;");
    };

    load_stage(0, 0);
    load_stage(1, 1);

    for (int s = 0; s < NSTG; s++) {
        if (s < NSTG - 1) asm volatile("cp.async.wait_group 1;" ::: "memory");
        else              asm volatile("cp.async.wait_group 0;" ::: "memory");
        __syncthreads();   // single barrier/stage; proves buffer (s-1)%3 drained

        const __half* st = smem + (s % NBUF) * STG_HALVES;
        const uint32_t sA = su32(st);
        const uint32_t sB = su32(st + A_HALVES);

        uint32_t a[2][4][4];                 // pipelined A fragments
        #pragma unroll
        for (int m = 0; m < 4; m++)          // k16 = 0
            ldsm4(a[0][m], sA + ((aRow + m * 16) * AST + aKoff) * 2);

        #pragma unroll
        for (int j = 0; j < 2; j++) {        // two k32 halves
            uint32_t b[4][4];
            #pragma unroll
            for (int g = 0; g < 4; g++)      // B frags for k16 = 2j and 2j+1
                ldsm4(b[g], sB + ((g * 32 + bRow) * BST + j * 32 + bKoff) * 2);
            #pragma unroll
            for (int m = 0; m < 4; m++)      // prefetch A for k16 = 2j+1
                ldsm4(a[1][m], sA + ((aRow + m * 16) * AST + (2 * j + 1) * 16 + aKoff) * 2);

            if (j == 0 && s + 2 < NSTG)      // cp burst hidden under MMA issue
                load_stage(s + 2, (s + 2) % NBUF);

            #pragma unroll
            for (int g = 0; g < 4; g++)      // k16 = 2j
                #pragma unroll
                for (int m = 0; m < 4; m++)
                    mma16816(acc[g][m], a[0][m], b[g]);
            if (j == 0) {
                #pragma unroll
                for (int m = 0; m < 4; m++)  // prefetch A for k16 = 2 while MMAs run
                    ldsm4(a[0][m], sA + ((aRow + m * 16) * AST + 2 * 16 + aKoff) * 2);
            }
            #pragma unroll
            for (int g = 0; g < 4; g++)      // k16 = 2j+1
                #pragma unroll
                for (int m = 0; m < 4; m++)
                    mma16816(acc[g][m], a[1][m], b[g] + 2);
        }
    }

    // ---- fused epilogue: bias + activations + cell update ----
    const int r0 = rowBase + warpM * 64 + (lane >> 2);
    const int c0 = colBase + warpN * 8 + (lane & 3) * 2;
    const size_t BH = (size_t)BB * HD;

    #pragma unroll
    for (int m = 0; m < 4; m++) {
        #pragma unroll
        for (int rr = 0; rr < 2; rr++) {
            const int row = r0 + m * 16 + rr * 8;
            #pragma unroll
            for (int cc = 0; cc < 2; cc++) {
                const int col = c0 + cc;
                const int ai = rr * 2 + cc;
                float gi = acc[0][m][ai] + bi[col];
                float gf = acc[1][m][ai] + bf[col];
                float go = acc[2][m][ai] + bo[col];
                float gc = acc[3][m][ai] + bc[col];
                float it = 1.f / (1.f + __expf(-gi));
                float ft = 1.f / (1.f + __expf(-gf));
                float ot = 1.f / (1.f + __expf(-go));
                float gt = 1.f - 2.f / (__expf(2.f * gc) + 1.f);
                float cv = cin[(size_t)row * HD + col];
                float ct = cv * ft + it * gt;
                float ht = ot * (1.f - 2.f / (__expf(2.f * ct) + 1.f));
                out[(size_t)row * HD + col] = ht;
                out[BH + (size_t)row * HD + col] = ct;
            }
        }
    }
}

extern "C" void kernel_launch(void* const* d_in, const int* in_sizes, int n_in,
                              void* d_out, int out_size) {
    (void)in_sizes; (void)n_in; (void)out_size;
    const float* x   = (const float*)d_in[0];
    const float* h   = (const float*)d_in[1];
    const float* c   = (const float*)d_in[2];
    const float* wxi = (const float*)d_in[3];
    const float* wxf = (const float*)d_in[4];
    const float* wxo = (const float*)d_in[5];
    const float* wxc = (const float*)d_in[6];
    const float* whi = (const float*)d_in[7];
    const float* whf = (const float*)d_in[8];
    const float* who = (const float*)d_in[9];
    const float* whc = (const float*)d_in[10];
    const float* bi  = (const float*)d_in[11];
    const float* bf  = (const float*)d_in[12];
    const float* bo  = (const float*)d_in[13];
    const float* bc  = (const float*)d_in[14];
    float* out = (float*)d_out;

    cudaFuncSetAttribute(lstm_hmma,
                         cudaFuncAttributeMaxDynamicSharedMemorySize, SMEM_BYTES);

    prep_a<<<(BB * KTOT / 4) / 256, 256>>>(x, h);
    prep_w<<<dim3(64, 64, 8), dim3(32, 8)>>>(wxi, wxf, wxo, wxc, whi, whf, who, whc);
    lstm_hmma<<<dim3(BB / BM, HD / BN), 256, SMEM_BYTES>>>(c, bi, bf, bo, bc, out);
}

// round 15
// speedup vs baseline: 1.0268x; 1.0268x over previous
#include <cuda_runtime.h>
#include <cuda_fp16.h>
#include <cstdint>

// ---------------------------------------------------------------------------
// LSTM cell, fp16 mma.sync (m16n8k16) GEMM + fused epilogue.
//  Pre-pass 1: WT[gate*2048+n][k] = half(W[k][n]),  k = [x-phase | h-phase]
//  Pre-pass 2: XH[b][k] = half([x|h][b][k])
//  Main: 128-thread CTA, 4 warps of 64x64 tiles over 128 rows x 128 gate-cols
//        (4 gates x 32), BK=64, NBUF=3, 2 CTAs/SM. B rows gate-interleaved in
//        smem so each warp combines all 4 gates in-register.
//  Out: [h_t ; c_t], fp32.
// ---------------------------------------------------------------------------

#define HD    2048
#define BB    4096
#define KTOT  4096
#define BM    128
#define BN    32            // cols per gate per CTA
#define BK    64            // halves per stage
#define NSTG  (KTOT/BK)     // 64
#define NBUF  3
#define AST   72            // smem stride in halves (padded, conflict-free)
#define BST   72
#define A_HALVES (BM*AST)                 // 9216
#define B_HALVES (128*BST)                // 9216  (4 gates x 32 cols)
#define STG_HALVES (A_HALVES + B_HALVES)  // 18432 (36864 B)
#define SMEM_BYTES (NBUF*STG_HALVES*2)    // 110592

__device__ __half d_WT[(size_t)4*2048*4096];   // 64 MB
__device__ __half d_XH[(size_t)4096*4096];     // 32 MB

__device__ __forceinline__ uint32_t su32(const void* p) {
    return (uint32_t)__cvta_generic_to_shared(p);
}
__device__ __forceinline__ void cp16(uint32_t d, const void* s) {
    asm volatile("cp.async.cg.shared.global [%0], [%1], 16;" :: "r"(d), "l"(s));
}
__device__ __forceinline__ void ldsm4(uint32_t* r, uint32_t a) {
    asm volatile("ldmatrix.sync.aligned.m8n8.x4.shared.b16 {%0,%1,%2,%3}, [%4];"
                 : "=r"(r[0]), "=r"(r[1]), "=r"(r[2]), "=r"(r[3]) : "r"(a));
}
__device__ __forceinline__ void mma16816(float* c, const uint32_t* a, const uint32_t* b) {
    asm volatile("mma.sync.aligned.m16n8k16.row.col.f32.f16.f16.f32 "
                 "{%0,%1,%2,%3}, {%4,%5,%6,%7}, {%8,%9}, {%0,%1,%2,%3};"
                 : "+f"(c[0]), "+f"(c[1]), "+f"(c[2]), "+f"(c[3])
                 : "r"(a[0]), "r"(a[1]), "r"(a[2]), "r"(a[3]), "r"(b[0]), "r"(b[1]));
}

// ---- pre-pass: transpose + convert weights: WT[g*2048+n][ph*2048+k] ----
__global__ void prep_w(const float* __restrict__ w0, const float* __restrict__ w1,
                       const float* __restrict__ w2, const float* __restrict__ w3,
                       const float* __restrict__ w4, const float* __restrict__ w5,
                       const float* __restrict__ w6, const float* __restrict__ w7) {
    __shared__ float t[32][33];
    const int z = blockIdx.z;                 // phase = z>>2, gate = z&3
    const float* W;
    switch (z) {
        case 0: W = w0; break; case 1: W = w1; break;
        case 2: W = w2; break; case 3: W = w3; break;
        case 4: W = w4; break; case 5: W = w5; break;
        case 6: W = w6; break; default: W = w7; break;
    }
    const int k0 = blockIdx.x * 32, n0 = blockIdx.y * 32;
    const int tx = threadIdx.x, ty = threadIdx.y;
    #pragma unroll
    for (int j = 0; j < 4; j++)
        t[ty + j * 8][tx] = W[(size_t)(k0 + ty + j * 8) * HD + n0 + tx];
    __syncthreads();
    const int gate = z & 3, phase = z >> 2;
    #pragma unroll
    for (int j = 0; j < 4; j++)
        d_WT[(size_t)(gate * 2048 + n0 + ty + j * 8) * KTOT + phase * 2048 + k0 + tx] =
            __float2half_rn(t[tx][ty + j * 8]);
}

// ---- pre-pass: pack + convert activations: XH[b] = [x | h] ----
__global__ void prep_a(const float* __restrict__ x, const float* __restrict__ h) {
    const int idx = blockIdx.x * 256 + threadIdx.x;    // one float4 -> 4 halves
    const int b = idx >> 10;
    const int k = (idx & 1023) * 4;
    const float* s = (k < HD) ? (x + (size_t)b * HD + k)
                              : (h + (size_t)b * HD + (k - HD));
    float4 v = *(const float4*)s;
    __half2 lo = __floats2half2_rn(v.x, v.y);
    __half2 hi = __floats2half2_rn(v.z, v.w);
    *(uint2*)(d_XH + (size_t)b * KTOT + k) =
        make_uint2(*(uint32_t*)&lo, *(uint32_t*)&hi);
}

// ---- main fused GEMM + LSTM epilogue ----
__global__ void __launch_bounds__(128, 2)
lstm_hmma(const float* __restrict__ cin,
          const float* __restrict__ bi, const float* __restrict__ bf,
          const float* __restrict__ bo, const float* __restrict__ bc,
          float* __restrict__ out) {
    extern __shared__ __half smem[];
    const int tid = threadIdx.x, lane = tid & 31, warp = tid >> 5;
    const int warpM = warp & 1;        // 2 warps along M (64 rows each)
    const int warpN = warp >> 1;       // 2 warps along N (64 gate-cols each)
    const int rowBase = blockIdx.x * BM;
    const int colBase = blockIdx.y * BN;

    // acc[mtile][n8tile][frag]; n8 tile t: gate = t>>1, col-half = t&1
    float acc[4][8][4];
    #pragma unroll
    for (int m = 0; m < 4; m++)
        #pragma unroll
        for (int t = 0; t < 8; t++)
            #pragma unroll
            for (int r = 0; r < 4; r++) acc[m][t][r] = 0.0f;

    // A ldsm4 lane offsets: matrices (m0-7,k0-7),(m8-15,k0-7),(m0-7,k8-15),(m8-15,k8-15)
    const int mi = lane >> 3;
    const int aRow = warpM * 64 + (lane & 7) + (mi & 1) * 8;     // + mtile*16
    const int aKoff = (mi >> 1) * 8;                             // + k16*16
    // B k32-packed ldsm4: matrices (n8, k0-7),(k8-15),(k16-23),(k24-31)
    const int bRowL = (lane & 7);                                // + n8row
    const int bKoff = mi * 8;                                    // + j*32

    // B smem row r (0..127) <-> gate = (r>>4)&3, col = colBase + (r>>6)*16 + (r&15)
    auto load_stage = [&](int s, int buf) {
        __half* st = smem + buf * STG_HALVES;
        const int kb = s * BK;
        #pragma unroll
        for (int i = 0; i < 8; i++) {                 // A: 1024 x 16B
            const int ci = i * 128 + tid;
            const int r = ci >> 3, kc = ci & 7;
            cp16(su32(st + r * AST + kc * 8),
                 d_XH + (size_t)(rowBase + r) * KTOT + kb + kc * 8);
        }
        __half* sb = st + A_HALVES;
        #pragma unroll
        for (int i = 0; i < 8; i++) {                 // B: 1024 x 16B
            const int ci = i * 128 + tid;
            const int n = ci >> 3, kc = ci & 7;
            const int g = (n >> 4) & 3;
            const int nc = colBase + (n >> 6) * 16 + (n & 15);
            cp16(su32(sb + n * BST + kc * 8),
                 d_WT + (size_t)(g * 2048 + nc) * KTOT + kb + kc * 8);
        }
        asm volatile("cp.async.commit_group;");
    };

    load_stage(0, 0);
    load_stage(1, 1);

    for (int s = 0; s < NSTG; s++) {
        if (s < NSTG - 1) asm volatile("cp.async.wait_group 1;" ::: "memory");
        else              asm volatile("cp.async.wait_group 0;" ::: "memory");
        __syncthreads();   // single barrier/stage; proves buffer (s-1)%3 drained

        if (s + 2 < NSTG) load_stage(s + 2, (s + 2) % NBUF);

        const __half* st = smem + (s % NBUF) * STG_HALVES;
        const uint32_t sA = su32(st);
        const uint32_t sB = su32(st + A_HALVES);

        #pragma unroll
        for (int j = 0; j < 2; j++) {                 // two k32 halves
            uint32_t b[8][4];
            #pragma unroll
            for (int t = 0; t < 8; t++)               // warp's 8 n8 tiles
                ldsm4(b[t], sB + ((warpN * 64 + t * 8 + bRowL) * BST
                                  + j * 32 + bKoff) * 2);
            #pragma unroll
            for (int hh = 0; hh < 2; hh++) {          // k16 = 2j + hh
                uint32_t a[4][4];
                #pragma unroll
                for (int m = 0; m < 4; m++)
                    ldsm4(a[m], sA + ((aRow + m * 16) * AST
                                      + (2 * j + hh) * 16 + aKoff) * 2);
                #pragma unroll
                for (int t = 0; t < 8; t++)
                    #pragma unroll
                    for (int m = 0; m < 4; m++)
                        mma16816(acc[m][t], a[m], &b[t][2 * hh]);
            }
        }
    }

    // ---- fused epilogue: bias + activations + cell update ----
    // thread frag: row = rowBase + warpM*64 + m*16 + (lane>>2) + rr*8
    //              col = colBase + warpN*16 + u*8 + (lane&3)*2 + cc   (u = t&1)
    //              gate g lives at t = 2g + u
    const int r0 = rowBase + warpM * 64 + (lane >> 2);
    const int c0 = colBase + warpN * 16 + (lane & 3) * 2;
    const size_t BH = (size_t)BB * HD;

    #pragma unroll
    for (int m = 0; m < 4; m++) {
        #pragma unroll
        for (int u = 0; u < 2; u++) {
            #pragma unroll
            for (int rr = 0; rr < 2; rr++) {
                const int row = r0 + m * 16 + rr * 8;
                #pragma unroll
                for (int cc = 0; cc < 2; cc++) {
                    const int col = c0 + u * 8 + cc;
                    const int ai = rr * 2 + cc;
                    float gi = acc[m][0 + u][ai] + bi[col];
                    float gf = acc[m][2 + u][ai] + bf[col];
                    float go = acc[m][4 + u][ai] + bo[col];
                    float gc = acc[m][6 + u][ai] + bc[col];
                    float it = 1.f / (1.f + __expf(-gi));
                    float ft = 1.f / (1.f + __expf(-gf));
                    float ot = 1.f / (1.f + __expf(-go));
                    float gt = 1.f - 2.f / (__expf(2.f * gc) + 1.f);
                    float cv = cin[(size_t)row * HD + col];
                    float ct = cv * ft + it * gt;
                    float ht = ot * (1.f - 2.f / (__expf(2.f * ct) + 1.f));
                    out[(size_t)row * HD + col] = ht;
                    out[BH + (size_t)row * HD + col] = ct;
                }
            }
        }
    }
}

extern "C" void kernel_launch(void* const* d_in, const int* in_sizes, int n_in,
                              void* d_out, int out_size) {
    (void)in_sizes; (void)n_in; (void)out_size;
    const float* x   = (const float*)d_in[0];
    const float* h   = (const float*)d_in[1];
    const float* c   = (const float*)d_in[2];
    const float* wxi = (const float*)d_in[3];
    const float* wxf = (const float*)d_in[4];
    const float* wxo = (const float*)d_in[5];
    const float* wxc = (const float*)d_in[6];
    const float* whi = (const float*)d_in[7];
    const float* whf = (const float*)d_in[8];
    const float* who = (const float*)d_in[9];
    const float* whc = (const float*)d_in[10];
    const float* bi  = (const float*)d_in[11];
    const float* bf  = (const float*)d_in[12];
    const float* bo  = (const float*)d_in[13];
    const float* bc  = (const float*)d_in[14];
    float* out = (float*)d_out;

    cudaFuncSetAttribute(lstm_hmma,
                         cudaFuncAttributeMaxDynamicSharedMemorySize, SMEM_BYTES);

    prep_a<<<(BB * KTOT / 4) / 256, 256>>>(x, h);
    prep_w<<<dim3(64, 64, 8), dim3(32, 8)>>>(wxi, wxf, wxo, wxc, whi, whf, who, whc);
    lstm_hmma<<<dim3(BB / BM, HD / BN), 128, SMEM_BYTES>>>(c, bi, bf, bo, bc, out);
}